// round 1
// baseline (speedup 1.0000x reference)
#include <cuda_runtime.h>
#include <cstdint>

// ---------------------------------------------------------------------------
// GAT_33938831573041: 3-layer GAT (PyG GATConv, concat=True, self-loops)
//   L1: F=128 -> H=7,C=32 (out 224) + relu
//   L2: F=224 -> H=6,C=32 (out 192) + relu
//   L3: F=192 -> H=6,C=40 (out 240)  -> d_out
// Strategy: CSR-by-dst build (int atomics only), tiled SGEMM for x@W,
// warp-per-(node,head) online-softmax aggregation with software pipelining.
// ---------------------------------------------------------------------------

#define NMAX 50000
#define EMAX 1200000

__device__ float g_feat[NMAX * 240];   // x@W of current layer
__device__ float g_buf [NMAX * 224];   // layer output (next layer input)
__device__ float g_als [NMAX * 7];
__device__ float g_ald [NMAX * 7];
__device__ int   g_deg [NMAX + 1];
__device__ int   g_off [NMAX + 1];
__device__ int   g_cur [NMAX];
__device__ int   g_csr [EMAX];
__device__ int   g_e64;

// ---------------------------------------------------------------- dtype sniff
__global__ void k_detect(const unsigned long long* ei, int nwords) {
    if (blockIdx.x == 0 && threadIdx.x == 0) {
        int ok = 1;
        int lim = nwords < 64 ? nwords : 64;
        for (int i = 0; i < lim; i++)
            if (ei[i] >= (1ull << 31)) ok = 0;
        g_e64 = ok;   // 1 => genuine int64 indices, 0 => int32 payload
    }
}

__device__ __forceinline__ int edge_val(const void* ei, int idx, int E, int which) {
    if (g_e64) return (int)((const long long*)ei)[(size_t)which * E + idx];
    return ((const int*)ei)[(size_t)which * E + idx];
}

// ---------------------------------------------------------------- CSR build
__global__ void k_init_deg(int n) {
    int i = blockIdx.x * blockDim.x + threadIdx.x;
    if (i < n) g_deg[i] = 1;            // self-loop contributes 1
}

__global__ void k_hist(const void* ei, int E) {
    int i = blockIdx.x * blockDim.x + threadIdx.x;
    if (i >= E) return;
    int d = edge_val(ei, i, E, 1);
    atomicAdd(&g_deg[d], 1);
}

__global__ void k_scan(int n) {        // exclusive scan g_deg -> g_off, copy to g_cur
    __shared__ int sh[1024];
    __shared__ int carry;
    if (threadIdx.x == 0) carry = 0;
    __syncthreads();
    for (int base = 0; base < n; base += 1024) {
        int i = base + threadIdx.x;
        int v = (i < n) ? g_deg[i] : 0;
        sh[threadIdx.x] = v;
        __syncthreads();
        #pragma unroll
        for (int off = 1; off < 1024; off <<= 1) {
            int t = (threadIdx.x >= off) ? sh[threadIdx.x - off] : 0;
            __syncthreads();
            sh[threadIdx.x] += t;
            __syncthreads();
        }
        int incl = sh[threadIdx.x];
        if (i < n) {
            int ex = carry + incl - v;
            g_off[i] = ex;
            g_cur[i] = ex;
        }
        __syncthreads();
        if (threadIdx.x == 0) carry += sh[1023];
        __syncthreads();
    }
    if (threadIdx.x == 0) g_off[n] = carry;
}

__global__ void k_scatter(const void* ei, int E, int n) {
    int i = blockIdx.x * blockDim.x + threadIdx.x;
    if (i >= E + n) return;
    int s, d;
    if (i < E) { s = edge_val(ei, i, E, 0); d = edge_val(ei, i, E, 1); }
    else       { s = d = i - E; }       // self-loop
    int slot = atomicAdd(&g_cur[d], 1);
    g_csr[slot] = s;
}

// ---------------------------------------------------------------- SGEMM
// C[M,Ncol] = A[M,K] @ B[K,Ncol], row-major. BM=BN=64, BK=16, 256 thr, 4x4/thr.
__global__ __launch_bounds__(256) void k_sgemm(
    const float* __restrict__ A, const float* __restrict__ B,
    float* __restrict__ C, int M, int K, int Ncol)
{
    __shared__ float As[16][64];
    __shared__ float Bs[16][64];
    int row0 = blockIdx.y * 64;
    int col0 = blockIdx.x * 64;
    int tid  = threadIdx.x;
    int tr   = tid >> 4;            // 0..15
    int tc   = tid & 15;            // 0..15
    float acc[4][4] = {};

    for (int k0 = 0; k0 < K; k0 += 16) {
        #pragma unroll
        for (int r = 0; r < 4; r++) {
            int e  = tid + r * 256;
            int m  = e >> 4;
            int kk = e & 15;
            int gr = row0 + m;
            As[kk][m] = (gr < M) ? A[(size_t)gr * K + k0 + kk] : 0.f;
        }
        #pragma unroll
        for (int r = 0; r < 4; r++) {
            int e  = tid + r * 256;
            int kk = e >> 6;
            int nn = e & 63;
            int gc = col0 + nn;
            Bs[kk][nn] = (gc < Ncol) ? B[(size_t)(k0 + kk) * Ncol + gc] : 0.f;
        }
        __syncthreads();
        #pragma unroll
        for (int kk = 0; kk < 16; kk++) {
            float a[4], b[4];
            #pragma unroll
            for (int i = 0; i < 4; i++) a[i] = As[kk][tr * 4 + i];
            #pragma unroll
            for (int j = 0; j < 4; j++) b[j] = Bs[kk][tc * 4 + j];
            #pragma unroll
            for (int i = 0; i < 4; i++)
                #pragma unroll
                for (int j = 0; j < 4; j++)
                    acc[i][j] += a[i] * b[j];
        }
        __syncthreads();
    }
    #pragma unroll
    for (int i = 0; i < 4; i++) {
        int gr = row0 + tr * 4 + i;
        if (gr >= M) continue;
        #pragma unroll
        for (int j = 0; j < 4; j++) {
            int gc = col0 + tc * 4 + j;
            if (gc < Ncol) C[(size_t)gr * Ncol + gc] = acc[i][j];
        }
    }
}

// ---------------------------------------------------------------- attn logits
template <int H, int C>
__global__ void k_logits(const float* __restrict__ feat,
                         const float* __restrict__ a_src,
                         const float* __restrict__ a_dst,
                         float* __restrict__ als, float* __restrict__ ald,
                         int n)
{
    int t = blockIdx.x * blockDim.x + threadIdx.x;
    if (t >= n * H) return;
    int nd = t / H, h = t % H;
    const float* row = feat + (size_t)nd * (H * C) + h * C;
    float ss = 0.f, sd = 0.f;
    #pragma unroll
    for (int c = 0; c < C; c++) {
        float v = row[c];
        ss += v * a_src[h * C + c];
        sd += v * a_dst[h * C + c];
    }
    als[t] = ss;
    ald[t] = sd;
}

// ---------------------------------------------------------------- aggregate
// warp per (node, head); lane = channel (CPL regs per lane for C>32).
// Online softmax over incoming edges, software pipeline depth 1 (payload) /
// 2 (csr index) to expose memory-level parallelism.
template <int H, int C, int CPL, bool RELU>
__global__ __launch_bounds__(256) void k_aggr(
    const float* __restrict__ feat, const float* __restrict__ als,
    const float* __restrict__ aldv, const float* __restrict__ bias,
    float* __restrict__ out, int n)
{
    int gw   = (blockIdx.x * blockDim.x + threadIdx.x) >> 5;
    int lane = threadIdx.x & 31;
    if (gw >= n * H) return;
    int nd = gw / H, h = gw % H;
    int beg = g_off[nd];
    int deg = g_off[nd + 1] - beg;

    float ald = aldv[nd * H + h];
    float m = -1e30f, s = 0.f;
    float acc[CPL];
    #pragma unroll
    for (int j = 0; j < CPL; j++) acc[j] = 0.f;

    // prologue: load edge 0 payload, edge 1 index
    int src0 = g_csr[beg];
    int srcA = (deg > 1) ? g_csr[beg + 1] : src0;
    float es = als[src0 * H + h];
    float v[CPL];
    {
        const float* frow = feat + (size_t)src0 * (H * C) + h * C;
        #pragma unroll
        for (int j = 0; j < CPL; j++) {
            int c = lane + 32 * j;
            v[j] = (c < C) ? __ldg(frow + c) : 0.f;
        }
    }

    for (int i = 0; i < deg; i++) {
        bool more = (i + 1 < deg);
        int srcB = (i + 2 < deg) ? g_csr[beg + i + 2] : srcA;
        float esn = 0.f;
        float vn[CPL];
        #pragma unroll
        for (int j = 0; j < CPL; j++) vn[j] = 0.f;
        if (more) {
            esn = als[srcA * H + h];
            const float* frow = feat + (size_t)srcA * (H * C) + h * C;
            #pragma unroll
            for (int j = 0; j < CPL; j++) {
                int c = lane + 32 * j;
                if (c < C) vn[j] = __ldg(frow + c);
            }
        }
        // ---- process current edge
        float e  = es + ald;
        e = (e > 0.f) ? e : 0.2f * e;          // leaky_relu(0.2)
        float mn = fmaxf(m, e);
        float f  = __expf(m - mn);             // m=-1e30 first iter -> 0
        float w  = __expf(e - mn);
        s = s * f + w;
        m = mn;
        #pragma unroll
        for (int j = 0; j < CPL; j++) acc[j] = acc[j] * f + w * v[j];
        // ---- rotate pipeline
        es = esn;
        #pragma unroll
        for (int j = 0; j < CPL; j++) v[j] = vn[j];
        srcA = srcB;
    }

    float inv = 1.f / s;
    #pragma unroll
    for (int j = 0; j < CPL; j++) {
        int c = lane + 32 * j;
        if (c < C) {
            float o = acc[j] * inv + bias[h * C + c];
            if (RELU) o = fmaxf(o, 0.f);
            out[(size_t)nd * (H * C) + h * C + c] = o;
        }
    }
}

// ---------------------------------------------------------------- launch
extern "C" void kernel_launch(void* const* d_in, const int* in_sizes, int n_in,
                              void* d_out, int out_size)
{
    const float* x   = (const float*)d_in[0];
    const void*  ei  = d_in[1];
    const float* W1  = (const float*)d_in[2];
    const float* a1s = (const float*)d_in[3];
    const float* a1d = (const float*)d_in[4];
    const float* b1  = (const float*)d_in[5];
    const float* W2  = (const float*)d_in[6];
    const float* a2s = (const float*)d_in[7];
    const float* a2d = (const float*)d_in[8];
    const float* b2  = (const float*)d_in[9];
    const float* W3  = (const float*)d_in[10];
    const float* a3s = (const float*)d_in[11];
    const float* a3d = (const float*)d_in[12];
    const float* b3  = (const float*)d_in[13];
    float* out = (float*)d_out;

    int E = in_sizes[1] / 2;
    int n = in_sizes[0] / 128;
    if (n > NMAX) n = NMAX;
    if (E + n > EMAX) E = EMAX - n;

    void *pf, *pb, *ps, *pd;
    cudaGetSymbolAddress(&pf, g_feat);
    cudaGetSymbolAddress(&pb, g_buf);
    cudaGetSymbolAddress(&ps, g_als);
    cudaGetSymbolAddress(&pd, g_ald);
    float* feat = (float*)pf;
    float* buf  = (float*)pb;
    float* als  = (float*)ps;
    float* ald  = (float*)pd;

    // CSR build
    k_detect<<<1, 32>>>((const unsigned long long*)ei, E);
    k_init_deg<<<(n + 255) / 256, 256>>>(n);
    k_hist<<<(E + 255) / 256, 256>>>(ei, E);
    k_scan<<<1, 1024>>>(n);
    k_scatter<<<(E + n + 255) / 256, 256>>>(ei, E, n);

    // Layer 1: F=128 -> H=7,C=32
    {
        dim3 grid((224 + 63) / 64, (n + 63) / 64);
        k_sgemm<<<grid, 256>>>(x, W1, feat, n, 128, 224);
        int nh = n * 7;
        k_logits<7, 32><<<(nh + 255) / 256, 256>>>(feat, a1s, a1d, als, ald, n);
        k_aggr<7, 32, 1, true><<<(nh + 7) / 8, 256>>>(feat, als, ald, b1, buf, n);
    }
    // Layer 2: F=224 -> H=6,C=32
    {
        dim3 grid((192 + 63) / 64, (n + 63) / 64);
        k_sgemm<<<grid, 256>>>(buf, W2, feat, n, 224, 192);
        int nh = n * 6;
        k_logits<6, 32><<<(nh + 255) / 256, 256>>>(feat, a2s, a2d, als, ald, n);
        k_aggr<6, 32, 1, true><<<(nh + 7) / 8, 256>>>(feat, als, ald, b2, buf, n);
    }
    // Layer 3: F=192 -> H=6,C=40 -> d_out
    {
        dim3 grid((240 + 63) / 64, (n + 63) / 64);
        k_sgemm<<<grid, 256>>>(buf, W3, feat, n, 192, 240);
        int nh = n * 6;
        k_logits<6, 40><<<(nh + 255) / 256, 256>>>(feat, a3s, a3d, als, ald, n);
        k_aggr<6, 40, 2, false><<<(nh + 7) / 8, 256>>>(feat, als, ald, b3, out, n);
    }
}

// round 2
// speedup vs baseline: 1.7604x; 1.7604x over previous
#include <cuda_runtime.h>
#include <cstdint>

// ---------------------------------------------------------------------------
// GAT_33938831573041: 3-layer GAT (PyG GATConv, concat=True, self-loops)
//   L1: F=128 -> H=7,C=32 (out 224) + relu
//   L2: F=224 -> H=6,C=32 (out 192) + relu
//   L3: F=192 -> H=6,C=40 (out 240)  -> d_out
// R2: parallel scan, warp-detect, 128x64 SGEMM (8x4/thr, float4),
//     max-pass + single-exp aggregation, warp-per-node head-loop (MLP=H).
// ---------------------------------------------------------------------------

#define NMAX 50000
#define EMAX 1200000

__device__ float g_feat[NMAX * 240];   // x@W of current layer
__device__ float g_buf [NMAX * 224];   // layer output (next layer input)
__device__ float g_als [NMAX * 7];
__device__ float g_ald [NMAX * 7];
__device__ float g_gm  [NMAX * 7];     // per (node,head) max logit
__device__ int   g_deg [NMAX + 1];
__device__ int   g_off [NMAX + 1];
__device__ int   g_cur [NMAX];
__device__ int   g_incl[NMAX];
__device__ int   g_part[128];
__device__ int   g_partx[128];
__device__ int   g_csr [EMAX];
__device__ int   g_e64;

// ---------------------------------------------------------------- dtype sniff
__global__ void k_detect(const unsigned long long* ei, int nwords) {
    int lane = threadIdx.x;
    int bad = 0;
    for (int i = lane; i < 64 && i < nwords; i += 32)
        if (ei[i] >= (1ull << 31)) bad = 1;
    unsigned m = __ballot_sync(0xffffffffu, bad);
    if (lane == 0) g_e64 = (m == 0);   // 1 => genuine int64 indices
}

__device__ __forceinline__ int edge_val(const void* ei, int idx, int E, int which) {
    if (g_e64) return (int)((const long long*)ei)[(size_t)which * E + idx];
    return ((const int*)ei)[(size_t)which * E + idx];
}

// ---------------------------------------------------------------- CSR build
__global__ void k_init_deg(int n) {
    int i = blockIdx.x * blockDim.x + threadIdx.x;
    if (i < n) g_deg[i] = 1;            // self-loop contributes 1
}

__global__ void k_hist(const void* ei, int E) {
    int i = blockIdx.x * blockDim.x + threadIdx.x;
    if (i >= E) return;
    int d = edge_val(ei, i, E, 1);
    atomicAdd(&g_deg[d], 1);
}

// 3-phase parallel exclusive scan of g_deg[0..n) -> g_off, g_cur, g_off[n]=total
__global__ void k_scan1(int n) {
    __shared__ int sh[1024];
    int tid = threadIdx.x;
    int i = blockIdx.x * 1024 + tid;
    int v = (i < n) ? g_deg[i] : 0;
    sh[tid] = v;
    __syncthreads();
    #pragma unroll
    for (int off = 1; off < 1024; off <<= 1) {
        int t = (tid >= off) ? sh[tid - off] : 0;
        __syncthreads();
        sh[tid] += t;
        __syncthreads();
    }
    if (i < n) g_incl[i] = sh[tid];
    if (tid == 1023) g_part[blockIdx.x] = sh[1023];
}

__global__ void k_scan2(int nb, int n) {
    __shared__ int sh[128];
    int tid = threadIdx.x;
    int v = (tid < nb) ? g_part[tid] : 0;
    sh[tid] = v;
    __syncthreads();
    #pragma unroll
    for (int off = 1; off < 128; off <<= 1) {
        int t = (tid >= off) ? sh[tid - off] : 0;
        __syncthreads();
        sh[tid] += t;
        __syncthreads();
    }
    if (tid < nb) g_partx[tid] = sh[tid] - v;
    if (tid == 127) g_off[n] = sh[127];
}

__global__ void k_scan3(int n) {
    int i = blockIdx.x * blockDim.x + threadIdx.x;
    if (i >= n) return;
    int ex = g_partx[i >> 10] + g_incl[i] - g_deg[i];
    g_off[i] = ex;
    g_cur[i] = ex;
}

__global__ void k_scatter(const void* ei, int E, int n) {
    int i = blockIdx.x * blockDim.x + threadIdx.x;
    if (i >= E + n) return;
    int s, d;
    if (i < E) { s = edge_val(ei, i, E, 0); d = edge_val(ei, i, E, 1); }
    else       { s = d = i - E; }       // self-loop
    int slot = atomicAdd(&g_cur[d], 1);
    g_csr[slot] = s;
}

// ---------------------------------------------------------------- SGEMM
// C[M,Ncol] = A[M,K] @ B[K,Ncol], row-major. BM=128, BN=64, BK=16,
// 256 threads, 8x4 per thread, float4 everywhere. K%16==0, Ncol%4==0.
__global__ __launch_bounds__(256) void k_sgemm(
    const float* __restrict__ A, const float* __restrict__ B,
    float* __restrict__ C, int M, int K, int Ncol)
{
    __shared__ float As[16][132];   // padded: conflict-light transposed stores
    __shared__ float Bs[16][64];
    int row0 = blockIdx.y * 128;
    int col0 = blockIdx.x * 64;
    int tid  = threadIdx.x;
    int tx   = tid & 15;            // column group (4 cols)
    int ty   = tid >> 4;            // row group (8 rows)
    float acc[8][4] = {};

    for (int k0 = 0; k0 < K; k0 += 16) {
        // A tile: 128 x 16, transposed into As[k][m]
        #pragma unroll
        for (int r = 0; r < 2; r++) {
            int id = tid + r * 256;
            int m  = id >> 2;
            int kq = id & 3;
            int gr = row0 + m;
            float4 av = make_float4(0.f, 0.f, 0.f, 0.f);
            if (gr < M) av = *(const float4*)(A + (size_t)gr * K + k0 + kq * 4);
            As[kq * 4 + 0][m] = av.x;
            As[kq * 4 + 1][m] = av.y;
            As[kq * 4 + 2][m] = av.z;
            As[kq * 4 + 3][m] = av.w;
        }
        // B tile: 16 x 64
        {
            int brow = tid >> 4;
            int cq   = tid & 15;
            int gc   = col0 + cq * 4;
            float4 bv = make_float4(0.f, 0.f, 0.f, 0.f);
            if (gc < Ncol) bv = *(const float4*)(B + (size_t)(k0 + brow) * Ncol + gc);
            *(float4*)&Bs[brow][cq * 4] = bv;
        }
        __syncthreads();
        #pragma unroll
        for (int kk = 0; kk < 16; kk++) {
            float4 a0 = *(const float4*)&As[kk][ty * 8];
            float4 a1 = *(const float4*)&As[kk][ty * 8 + 4];
            float4 bv = *(const float4*)&Bs[kk][tx * 4];
            float a[8] = {a0.x, a0.y, a0.z, a0.w, a1.x, a1.y, a1.z, a1.w};
            float b[4] = {bv.x, bv.y, bv.z, bv.w};
            #pragma unroll
            for (int i = 0; i < 8; i++)
                #pragma unroll
                for (int j = 0; j < 4; j++)
                    acc[i][j] += a[i] * b[j];
        }
        __syncthreads();
    }
    #pragma unroll
    for (int i = 0; i < 8; i++) {
        int gr = row0 + ty * 8 + i;
        if (gr >= M) continue;
        int gc = col0 + tx * 4;
        if (gc < Ncol)
            *(float4*)(C + (size_t)gr * Ncol + gc) =
                make_float4(acc[i][0], acc[i][1], acc[i][2], acc[i][3]);
    }
}

// ---------------------------------------------------------------- attn logits
template <int H, int C>
__global__ void k_logits(const float* __restrict__ feat,
                         const float* __restrict__ a_src,
                         const float* __restrict__ a_dst,
                         float* __restrict__ als, float* __restrict__ ald,
                         int n)
{
    int t = blockIdx.x * blockDim.x + threadIdx.x;
    if (t >= n * H) return;
    int nd = t / H, h = t % H;
    const float4* row = (const float4*)(feat + (size_t)nd * (H * C) + h * C);
    const float4* as  = (const float4*)(a_src + h * C);
    const float4* ad  = (const float4*)(a_dst + h * C);
    float ss = 0.f, sd = 0.f;
    #pragma unroll
    for (int c = 0; c < C / 4; c++) {
        float4 v = row[c], s4 = as[c], d4 = ad[c];
        ss += v.x * s4.x + v.y * s4.y + v.z * s4.z + v.w * s4.w;
        sd += v.x * d4.x + v.y * d4.y + v.z * d4.z + v.w * d4.w;
    }
    als[t] = ss;
    ald[t] = sd;
}

// ---------------------------------------------------------------- max pass
// warp per node; lanes 0..H-1 each own one head. One coalesced 28B als read
// per edge, no feat traffic.
template <int H>
__global__ __launch_bounds__(256) void k_maxp(
    const float* __restrict__ als, const float* __restrict__ aldv,
    float* __restrict__ gm, int n)
{
    int gw   = (blockIdx.x * blockDim.x + threadIdx.x) >> 5;
    int lane = threadIdx.x & 31;
    if (gw >= n) return;
    int beg = g_off[gw], end = g_off[gw + 1];
    float ald = (lane < H) ? aldv[gw * H + lane] : 0.f;
    float m = -1e30f;
    int src = g_csr[beg];
    for (int i = beg; i < end; i++) {
        int srcN = (i + 1 < end) ? g_csr[i + 1] : src;
        float a = (lane < H) ? als[(size_t)src * H + lane] : 0.f;
        float e = a + ald;
        e = (e > 0.f) ? e : 0.2f * e;
        m = fmaxf(m, e);
        src = srcN;
    }
    if (lane < H) gm[gw * H + lane] = m;
}

// ---------------------------------------------------------------- aggregate
// warp per node, loop over heads inside (MLP = H independent feat loads/edge),
// single exp per (edge,head) thanks to precomputed max.
template <int H, int C, int CPL, bool RELU>
__global__ __launch_bounds__(256) void k_aggr(
    const float* __restrict__ feat, const float* __restrict__ als,
    const float* __restrict__ aldv, const float* __restrict__ gm,
    const float* __restrict__ bias, float* __restrict__ out, int n)
{
    const unsigned FULL = 0xffffffffu;
    int gw   = (blockIdx.x * blockDim.x + threadIdx.x) >> 5;
    int lane = threadIdx.x & 31;
    if (gw >= n) return;
    int nd  = gw;
    int beg = g_off[nd], end = g_off[nd + 1];

    float aldL = (lane < H) ? aldv[nd * H + lane] : 0.f;
    float mL   = (lane < H) ? gm  [nd * H + lane] : 0.f;
    float aldh[H], Mh[H];
    #pragma unroll
    for (int h = 0; h < H; h++) {
        aldh[h] = __shfl_sync(FULL, aldL, h);
        Mh[h]   = __shfl_sync(FULL, mL, h);
    }
    float s[H];
    float acc[H][CPL];
    #pragma unroll
    for (int h = 0; h < H; h++) {
        s[h] = 0.f;
        #pragma unroll
        for (int j = 0; j < CPL; j++) acc[h][j] = 0.f;
    }

    int src   = g_csr[beg];
    float alsL = (lane < H) ? als[(size_t)src * H + lane] : 0.f;

    for (int i = beg; i < end; i++) {
        bool more = (i + 1 < end);
        int srcN = more ? g_csr[i + 1] : src;
        // issue all H feat loads for the current edge (MLP)
        float v[H][CPL];
        #pragma unroll
        for (int h = 0; h < H; h++) {
            const float* fr = feat + (size_t)src * (H * C) + h * C;
            #pragma unroll
            for (int j = 0; j < CPL; j++) {
                int c = lane + 32 * j;
                v[h][j] = (c < C) ? __ldg(fr + c) : 0.f;
            }
        }
        float alsN = (more && lane < H) ? als[(size_t)srcN * H + lane] : 0.f;
        #pragma unroll
        for (int h = 0; h < H; h++) {
            float e = __shfl_sync(FULL, alsL, h) + aldh[h];
            e = (e > 0.f) ? e : 0.2f * e;
            float w = __expf(e - Mh[h]);
            s[h] += w;
            #pragma unroll
            for (int j = 0; j < CPL; j++) acc[h][j] += w * v[h][j];
        }
        alsL = more ? alsN : alsL;
        src  = srcN;
    }

    #pragma unroll
    for (int h = 0; h < H; h++) {
        float inv = 1.f / s[h];
        #pragma unroll
        for (int j = 0; j < CPL; j++) {
            int c = lane + 32 * j;
            if (c < C) {
                float o = acc[h][j] * inv + bias[h * C + c];
                if (RELU) o = fmaxf(o, 0.f);
                out[(size_t)nd * (H * C) + h * C + c] = o;
            }
        }
    }
}

// ---------------------------------------------------------------- launch
extern "C" void kernel_launch(void* const* d_in, const int* in_sizes, int n_in,
                              void* d_out, int out_size)
{
    const float* x   = (const float*)d_in[0];
    const void*  ei  = d_in[1];
    const float* W1  = (const float*)d_in[2];
    const float* a1s = (const float*)d_in[3];
    const float* a1d = (const float*)d_in[4];
    const float* b1  = (const float*)d_in[5];
    const float* W2  = (const float*)d_in[6];
    const float* a2s = (const float*)d_in[7];
    const float* a2d = (const float*)d_in[8];
    const float* b2  = (const float*)d_in[9];
    const float* W3  = (const float*)d_in[10];
    const float* a3s = (const float*)d_in[11];
    const float* a3d = (const float*)d_in[12];
    const float* b3  = (const float*)d_in[13];
    float* out = (float*)d_out;

    int E = in_sizes[1] / 2;
    int n = in_sizes[0] / 128;
    if (n > NMAX) n = NMAX;
    if (E + n > EMAX) E = EMAX - n;

    void *pf, *pb, *ps, *pd, *pm;
    cudaGetSymbolAddress(&pf, g_feat);
    cudaGetSymbolAddress(&pb, g_buf);
    cudaGetSymbolAddress(&ps, g_als);
    cudaGetSymbolAddress(&pd, g_ald);
    cudaGetSymbolAddress(&pm, g_gm);
    float* feat = (float*)pf;
    float* buf  = (float*)pb;
    float* als  = (float*)ps;
    float* ald  = (float*)pd;
    float* gm   = (float*)pm;

    // CSR build
    k_detect<<<1, 32>>>((const unsigned long long*)ei, E);
    k_init_deg<<<(n + 255) / 256, 256>>>(n);
    k_hist<<<(E + 255) / 256, 256>>>(ei, E);
    int nb = (n + 1023) / 1024;
    k_scan1<<<nb, 1024>>>(n);
    k_scan2<<<1, 128>>>(nb, n);
    k_scan3<<<(n + 255) / 256, 256>>>(n);
    k_scatter<<<(E + n + 255) / 256, 256>>>(ei, E, n);

    int wgrid = (n + 7) / 8;   // warp-per-node kernels, 8 warps/block

    // Layer 1: F=128 -> H=7,C=32
    {
        dim3 grid((224 + 63) / 64, (n + 127) / 128);
        k_sgemm<<<grid, 256>>>(x, W1, feat, n, 128, 224);
        int nh = n * 7;
        k_logits<7, 32><<<(nh + 255) / 256, 256>>>(feat, a1s, a1d, als, ald, n);
        k_maxp<7><<<wgrid, 256>>>(als, ald, gm, n);
        k_aggr<7, 32, 1, true><<<wgrid, 256>>>(feat, als, ald, gm, b1, buf, n);
    }
    // Layer 2: F=224 -> H=6,C=32
    {
        dim3 grid((192 + 63) / 64, (n + 127) / 128);
        k_sgemm<<<grid, 256>>>(buf, W2, feat, n, 224, 192);
        int nh = n * 6;
        k_logits<6, 32><<<(nh + 255) / 256, 256>>>(feat, a2s, a2d, als, ald, n);
        k_maxp<6><<<wgrid, 256>>>(als, ald, gm, n);
        k_aggr<6, 32, 1, true><<<wgrid, 256>>>(feat, als, ald, gm, b2, buf, n);
    }
    // Layer 3: F=192 -> H=6,C=40 -> d_out
    {
        dim3 grid((240 + 63) / 64, (n + 127) / 128);
        k_sgemm<<<grid, 256>>>(buf, W3, feat, n, 192, 240);
        int nh = n * 6;
        k_logits<6, 40><<<(nh + 255) / 256, 256>>>(feat, a3s, a3d, als, ald, n);
        k_maxp<6><<<wgrid, 256>>>(als, ald, gm, n);
        k_aggr<6, 40, 2, false><<<wgrid, 256>>>(feat, als, ald, gm, b3, out, n);
    }
}

// round 5
// speedup vs baseline: 2.2959x; 1.3042x over previous
#include <cuda_runtime.h>
#include <cstdint>

// ---------------------------------------------------------------------------
// GAT_33938831573041: 3-layer GAT (PyG GATConv, concat=True, self-loops)
//   L1: F=128 -> H=7,C=32 (out 224) + relu
//   L2: F=224 -> H=6,C=32 (out 192) + relu
//   L3: F=192 -> H=6,C=40 (out 240)  -> d_out
// R4 (= R3 resubmit after infra failure): no max pass (safe exp),
//     float4 lane-parallel aggregation (1 MUFU warp-instr/edge),
//     register-staged double-buffered SGEMM, __ldg on gather loads.
// ---------------------------------------------------------------------------

#define NMAX 50000
#define EMAX 1200000

__device__ float g_feat[NMAX * 240];   // x@W of current layer
__device__ float g_buf [NMAX * 224];   // layer output (next layer input)
__device__ float g_als [NMAX * 7];
__device__ float g_ald [NMAX * 7];
__device__ int   g_deg [NMAX + 1];
__device__ int   g_off [NMAX + 1];
__device__ int   g_cur [NMAX];
__device__ int   g_incl[NMAX];
__device__ int   g_part[128];
__device__ int   g_partx[128];
__device__ int   g_csr [EMAX];
__device__ int   g_e64;

// ---------------------------------------------------------------- dtype sniff
__global__ void k_detect(const unsigned long long* ei, int nwords) {
    int lane = threadIdx.x;
    int bad = 0;
    for (int i = lane; i < 64 && i < nwords; i += 32)
        if (ei[i] >= (1ull << 31)) bad = 1;
    unsigned m = __ballot_sync(0xffffffffu, bad);
    if (lane == 0) g_e64 = (m == 0);   // 1 => genuine int64 indices
}

__device__ __forceinline__ int edge_val(const void* ei, int idx, int E, int which) {
    if (g_e64) return (int)((const long long*)ei)[(size_t)which * E + idx];
    return ((const int*)ei)[(size_t)which * E + idx];
}

// ---------------------------------------------------------------- CSR build
__global__ void k_init_deg(int n) {
    int i = blockIdx.x * blockDim.x + threadIdx.x;
    if (i < n) g_deg[i] = 1;            // self-loop contributes 1
}

__global__ void k_hist(const void* ei, int E) {
    int i = blockIdx.x * blockDim.x + threadIdx.x;
    if (i >= E) return;
    int d = edge_val(ei, i, E, 1);
    atomicAdd(&g_deg[d], 1);
}

// 3-phase parallel exclusive scan of g_deg[0..n) -> g_off, g_cur, g_off[n]=total
__global__ void k_scan1(int n) {
    __shared__ int sh[1024];
    int tid = threadIdx.x;
    int i = blockIdx.x * 1024 + tid;
    int v = (i < n) ? g_deg[i] : 0;
    sh[tid] = v;
    __syncthreads();
    #pragma unroll
    for (int off = 1; off < 1024; off <<= 1) {
        int t = (tid >= off) ? sh[tid - off] : 0;
        __syncthreads();
        sh[tid] += t;
        __syncthreads();
    }
    if (i < n) g_incl[i] = sh[tid];
    if (tid == 1023) g_part[blockIdx.x] = sh[1023];
}

__global__ void k_scan2(int nb, int n) {
    __shared__ int sh[128];
    int tid = threadIdx.x;
    int v = (tid < nb) ? g_part[tid] : 0;
    sh[tid] = v;
    __syncthreads();
    #pragma unroll
    for (int off = 1; off < 128; off <<= 1) {
        int t = (tid >= off) ? sh[tid - off] : 0;
        __syncthreads();
        sh[tid] += t;
        __syncthreads();
    }
    if (tid < nb) g_partx[tid] = sh[tid] - v;
    if (tid == 127) g_off[n] = sh[127];
}

__global__ void k_scan3(int n) {
    int i = blockIdx.x * blockDim.x + threadIdx.x;
    if (i >= n) return;
    int ex = g_partx[i >> 10] + g_incl[i] - g_deg[i];
    g_off[i] = ex;
    g_cur[i] = ex;
}

__global__ void k_scatter(const void* ei, int E, int n) {
    int i = blockIdx.x * blockDim.x + threadIdx.x;
    if (i >= E + n) return;
    int s, d;
    if (i < E) { s = edge_val(ei, i, E, 0); d = edge_val(ei, i, E, 1); }
    else       { s = d = i - E; }       // self-loop
    int slot = atomicAdd(&g_cur[d], 1);
    g_csr[slot] = s;
}

// ---------------------------------------------------------------- SGEMM
// C[M,Ncol] = A[M,K] @ B[K,Ncol], row-major. BM=128, BN=64, BK=16,
// 256 threads, 8x4 per thread, float4, register-staged double buffer.
__global__ __launch_bounds__(256) void k_sgemm(
    const float* __restrict__ A, const float* __restrict__ B,
    float* __restrict__ C, int M, int K, int Ncol)
{
    __shared__ float As[16][132];
    __shared__ float Bs[16][64];
    int row0 = blockIdx.y * 128;
    int col0 = blockIdx.x * 64;
    int tid  = threadIdx.x;
    int tx   = tid & 15;            // column group (4 cols)
    int ty   = tid >> 4;            // row group (8 rows)
    float acc[8][4] = {};

    // per-thread load coordinates
    int am[2], akq[2];
    #pragma unroll
    for (int r = 0; r < 2; r++) {
        int id = tid + r * 256;
        am[r]  = id >> 2;
        akq[r] = id & 3;
    }
    int brow = tid >> 4;
    int bcq  = tid & 15;
    int bgc  = col0 + bcq * 4;

    // prologue: tile 0 -> smem
    #pragma unroll
    for (int r = 0; r < 2; r++) {
        int gr = row0 + am[r];
        float4 av = make_float4(0.f, 0.f, 0.f, 0.f);
        if (gr < M) av = *(const float4*)(A + (size_t)gr * K + akq[r] * 4);
        As[akq[r] * 4 + 0][am[r]] = av.x;
        As[akq[r] * 4 + 1][am[r]] = av.y;
        As[akq[r] * 4 + 2][am[r]] = av.z;
        As[akq[r] * 4 + 3][am[r]] = av.w;
    }
    {
        float4 bv = make_float4(0.f, 0.f, 0.f, 0.f);
        if (bgc < Ncol) bv = *(const float4*)(B + (size_t)brow * Ncol + bgc);
        *(float4*)&Bs[brow][bcq * 4] = bv;
    }
    __syncthreads();

    for (int k0 = 0; k0 < K; k0 += 16) {
        bool hasNext = (k0 + 16) < K;
        float4 an[2], bn;
        if (hasNext) {
            #pragma unroll
            for (int r = 0; r < 2; r++) {
                int gr = row0 + am[r];
                an[r] = make_float4(0.f, 0.f, 0.f, 0.f);
                if (gr < M) an[r] = *(const float4*)(A + (size_t)gr * K + k0 + 16 + akq[r] * 4);
            }
            bn = make_float4(0.f, 0.f, 0.f, 0.f);
            if (bgc < Ncol) bn = *(const float4*)(B + (size_t)(k0 + 16 + brow) * Ncol + bgc);
        }
        #pragma unroll
        for (int kk = 0; kk < 16; kk++) {
            float4 a0 = *(const float4*)&As[kk][ty * 8];
            float4 a1 = *(const float4*)&As[kk][ty * 8 + 4];
            float4 bv = *(const float4*)&Bs[kk][tx * 4];
            float a[8] = {a0.x, a0.y, a0.z, a0.w, a1.x, a1.y, a1.z, a1.w};
            float b[4] = {bv.x, bv.y, bv.z, bv.w};
            #pragma unroll
            for (int i = 0; i < 8; i++)
                #pragma unroll
                for (int j = 0; j < 4; j++)
                    acc[i][j] += a[i] * b[j];
        }
        if (hasNext) {
            __syncthreads();
            #pragma unroll
            for (int r = 0; r < 2; r++) {
                As[akq[r] * 4 + 0][am[r]] = an[r].x;
                As[akq[r] * 4 + 1][am[r]] = an[r].y;
                As[akq[r] * 4 + 2][am[r]] = an[r].z;
                As[akq[r] * 4 + 3][am[r]] = an[r].w;
            }
            *(float4*)&Bs[brow][bcq * 4] = bn;
            __syncthreads();
        }
    }
    #pragma unroll
    for (int i = 0; i < 8; i++) {
        int gr = row0 + ty * 8 + i;
        if (gr >= M) continue;
        int gc = col0 + tx * 4;
        if (gc < Ncol)
            *(float4*)(C + (size_t)gr * Ncol + gc) =
                make_float4(acc[i][0], acc[i][1], acc[i][2], acc[i][3]);
    }
}

// ---------------------------------------------------------------- attn logits
template <int H, int C>
__global__ void k_logits(const float* __restrict__ feat,
                         const float* __restrict__ a_src,
                         const float* __restrict__ a_dst,
                         float* __restrict__ als, float* __restrict__ ald,
                         int n)
{
    int t = blockIdx.x * blockDim.x + threadIdx.x;
    if (t >= n * H) return;
    int nd = t / H, h = t % H;
    const float4* row = (const float4*)(feat + (size_t)nd * (H * C) + h * C);
    const float4* as  = (const float4*)(a_src + h * C);
    const float4* ad  = (const float4*)(a_dst + h * C);
    float ss = 0.f, sd = 0.f;
    #pragma unroll
    for (int c = 0; c < C / 4; c++) {
        float4 v = row[c], s4 = as[c], d4 = ad[c];
        ss += v.x * s4.x + v.y * s4.y + v.z * s4.z + v.w * s4.w;
        sd += v.x * d4.x + v.y * d4.y + v.z * d4.z + v.w * d4.w;
    }
    als[t] = ss;
    ald[t] = sd;
}

// ---------------------------------------------------------------- aggregate
// warp per node. Softmax without max-shift (logits tiny; clamp@80 is a no-op
// safety). Row gathered as float4 chunks: chunk j = f4 index j*32+lane.
// One MUFU warp-instruction per edge (exp on lanes 0..H-1), weights routed
// by shfl with precomputed head selectors. Depth-2 src/payload pipeline.
template <int H, int C, bool RELU>
__global__ __launch_bounds__(256) void k_aggr(
    const float* __restrict__ feat, const float* __restrict__ als,
    const float* __restrict__ aldv, const float* __restrict__ bias,
    float* __restrict__ out, int n)
{
    constexpr int HC  = H * C;
    constexpr int NF4 = HC / 4;
    const unsigned FULL = 0xffffffffu;
    int gw   = (blockIdx.x * blockDim.x + threadIdx.x) >> 5;
    int lane = threadIdx.x & 31;
    if (gw >= n) return;
    int beg = g_off[gw], end = g_off[gw + 1];

    int  f4a = lane, f4b = 32 + lane;
    bool actB = f4b < NF4;                 // chunk A always active (NF4 >= 32)
    int  hA = (4 * f4a) / C;
    int  hB = actB ? (4 * f4b) / C : 0;

    float aldL = (lane < H) ? aldv[gw * H + lane] : 0.f;
    float s = 0.f;
    float4 accA = make_float4(0.f, 0.f, 0.f, 0.f);
    float4 accB = make_float4(0.f, 0.f, 0.f, 0.f);

    // pipeline prologue
    int src  = g_csr[beg];
    int srcA = (beg + 1 < end) ? g_csr[beg + 1] : src;
    float  alsC = (lane < H) ? __ldg(als + (size_t)src * H + lane) : 0.f;
    float4 vA = __ldg((const float4*)(feat + (size_t)src * HC) + f4a);
    float4 vB = actB ? __ldg((const float4*)(feat + (size_t)src * HC) + f4b)
                     : make_float4(0.f, 0.f, 0.f, 0.f);

    for (int i = beg; i < end; i++) {
        bool more = (i + 1 < end);
        int srcB = (i + 2 < end) ? g_csr[i + 2] : srcA;
        float  alsN = 0.f;
        float4 vAn = make_float4(0.f, 0.f, 0.f, 0.f);
        float4 vBn = make_float4(0.f, 0.f, 0.f, 0.f);
        if (more) {
            alsN = (lane < H) ? __ldg(als + (size_t)srcA * H + lane) : 0.f;
            vAn = __ldg((const float4*)(feat + (size_t)srcA * HC) + f4a);
            if (actB) vBn = __ldg((const float4*)(feat + (size_t)srcA * HC) + f4b);
        }
        // ---- process current edge
        float e = alsC + aldL;
        e = (e > 0.f) ? e : 0.2f * e;
        e = fminf(e, 80.f);
        float w = (lane < H) ? __expf(e) : 0.f;
        s += w;
        float wA = __shfl_sync(FULL, w, hA);
        float wB = __shfl_sync(FULL, w, hB);
        accA.x += wA * vA.x; accA.y += wA * vA.y;
        accA.z += wA * vA.z; accA.w += wA * vA.w;
        accB.x += wB * vB.x; accB.y += wB * vB.y;
        accB.z += wB * vB.z; accB.w += wB * vB.w;
        // ---- rotate
        alsC = alsN; vA = vAn; vB = vBn; srcA = srcB;
    }

    float inv  = (lane < H) ? 1.f / s : 0.f;
    float invA = __shfl_sync(FULL, inv, hA);
    float invB = __shfl_sync(FULL, inv, hB);
    {
        float4 b4 = *(const float4*)(bias + 4 * f4a);
        float4 o;
        o.x = accA.x * invA + b4.x; o.y = accA.y * invA + b4.y;
        o.z = accA.z * invA + b4.z; o.w = accA.w * invA + b4.w;
        if (RELU) {
            o.x = fmaxf(o.x, 0.f); o.y = fmaxf(o.y, 0.f);
            o.z = fmaxf(o.z, 0.f); o.w = fmaxf(o.w, 0.f);
        }
        *(float4*)(out + (size_t)gw * HC + 4 * f4a) = o;
    }
    if (actB) {
        float4 b4 = *(const float4*)(bias + 4 * f4b);
        float4 o;
        o.x = accB.x * invB + b4.x; o.y = accB.y * invB + b4.y;
        o.z = accB.z * invB + b4.z; o.w = accB.w * invB + b4.w;
        if (RELU) {
            o.x = fmaxf(o.x, 0.f); o.y = fmaxf(o.y, 0.f);
            o.z = fmaxf(o.z, 0.f); o.w = fmaxf(o.w, 0.f);
        }
        *(float4*)(out + (size_t)gw * HC + 4 * f4b) = o;
    }
}

// ---------------------------------------------------------------- launch
extern "C" void kernel_launch(void* const* d_in, const int* in_sizes, int n_in,
                              void* d_out, int out_size)
{
    const float* x   = (const float*)d_in[0];
    const void*  ei  = d_in[1];
    const float* W1  = (const float*)d_in[2];
    const float* a1s = (const float*)d_in[3];
    const float* a1d = (const float*)d_in[4];
    const float* b1  = (const float*)d_in[5];
    const float* W2  = (const float*)d_in[6];
    const float* a2s = (const float*)d_in[7];
    const float* a2d = (const float*)d_in[8];
    const float* b2  = (const float*)d_in[9];
    const float* W3  = (const float*)d_in[10];
    const float* a3s = (const float*)d_in[11];
    const float* a3d = (const float*)d_in[12];
    const float* b3  = (const float*)d_in[13];
    float* out = (float*)d_out;

    int E = in_sizes[1] / 2;
    int n = in_sizes[0] / 128;
    if (n > NMAX) n = NMAX;
    if (E + n > EMAX) E = EMAX - n;

    void *pf, *pb, *ps, *pd;
    cudaGetSymbolAddress(&pf, g_feat);
    cudaGetSymbolAddress(&pb, g_buf);
    cudaGetSymbolAddress(&ps, g_als);
    cudaGetSymbolAddress(&pd, g_ald);
    float* feat = (float*)pf;
    float* buf  = (float*)pb;
    float* als  = (float*)ps;
    float* ald  = (float*)pd;

    // CSR build
    k_detect<<<1, 32>>>((const unsigned long long*)ei, E);
    k_init_deg<<<(n + 255) / 256, 256>>>(n);
    k_hist<<<(E + 255) / 256, 256>>>(ei, E);
    int nb = (n + 1023) / 1024;
    k_scan1<<<nb, 1024>>>(n);
    k_scan2<<<1, 128>>>(nb, n);
    k_scan3<<<(n + 255) / 256, 256>>>(n);
    k_scatter<<<(E + n + 255) / 256, 256>>>(ei, E, n);

    int wgrid = (n + 7) / 8;   // warp-per-node kernels, 8 warps/block

    // Layer 1: F=128 -> H=7,C=32
    {
        dim3 grid((224 + 63) / 64, (n + 127) / 128);
        k_sgemm<<<grid, 256>>>(x, W1, feat, n, 128, 224);
        int nh = n * 7;
        k_logits<7, 32><<<(nh + 255) / 256, 256>>>(feat, a1s, a1d, als, ald, n);
        k_aggr<7, 32, true><<<wgrid, 256>>>(feat, als, ald, b1, buf, n);
    }
    // Layer 2: F=224 -> H=6,C=32
    {
        dim3 grid((192 + 63) / 64, (n + 127) / 128);
        k_sgemm<<<grid, 256>>>(buf, W2, feat, n, 224, 192);
        int nh = n * 6;
        k_logits<6, 32><<<(nh + 255) / 256, 256>>>(feat, a2s, a2d, als, ald, n);
        k_aggr<6, 32, true><<<wgrid, 256>>>(feat, als, ald, b2, buf, n);
    }
    // Layer 3: F=192 -> H=6,C=40 -> d_out
    {
        dim3 grid((240 + 63) / 64, (n + 127) / 128);
        k_sgemm<<<grid, 256>>>(buf, W3, feat, n, 192, 240);
        int nh = n * 6;
        k_logits<6, 40><<<(nh + 255) / 256, 256>>>(feat, a3s, a3d, als, ald, n);
        k_aggr<6, 40, false><<<wgrid, 256>>>(feat, als, ald, b3, out, n);
    }
}

// round 6
// speedup vs baseline: 2.3644x; 1.0298x over previous
#include <cuda_runtime.h>
#include <cuda_fp16.h>
#include <cstdint>

// ---------------------------------------------------------------------------
// GAT_33938831573041: 3-layer GAT (PyG GATConv, concat=True, self-loops)
//   L1: F=128 -> H=7,C=32 (out 224) + relu
//   L2: F=224 -> H=6,C=32 (out 192) + relu
//   L3: F=192 -> H=6,C=40 (out 240)  -> d_out
// R6: feat stored as fp16 (halves edge-gather L2 traffic; fp32 accumulate),
//     1 uint4 load per edge-lane (8 channels), SGEMM fp16 epilogue,
//     half2 logits. Everything else as R4.
// ---------------------------------------------------------------------------

#define NMAX 50000
#define EMAX 1200000

__device__ unsigned short g_feat[NMAX * 240];  // x@W of current layer (fp16)
__device__ float g_buf [NMAX * 224];   // layer output (next layer input, fp32)
__device__ float g_als [NMAX * 7];
__device__ float g_ald [NMAX * 7];
__device__ int   g_deg [NMAX + 1];
__device__ int   g_off [NMAX + 1];
__device__ int   g_cur [NMAX];
__device__ int   g_incl[NMAX];
__device__ int   g_part[128];
__device__ int   g_partx[128];
__device__ int   g_csr [EMAX];
__device__ int   g_e64;

// ---------------------------------------------------------------- dtype sniff
__global__ void k_detect(const unsigned long long* ei, int nwords) {
    int lane = threadIdx.x;
    int bad = 0;
    for (int i = lane; i < 64 && i < nwords; i += 32)
        if (ei[i] >= (1ull << 31)) bad = 1;
    unsigned m = __ballot_sync(0xffffffffu, bad);
    if (lane == 0) g_e64 = (m == 0);   // 1 => genuine int64 indices
}

__device__ __forceinline__ int edge_val(const void* ei, int idx, int E, int which) {
    if (g_e64) return (int)((const long long*)ei)[(size_t)which * E + idx];
    return ((const int*)ei)[(size_t)which * E + idx];
}

// ---------------------------------------------------------------- CSR build
__global__ void k_init_deg(int n) {
    int i = blockIdx.x * blockDim.x + threadIdx.x;
    if (i < n) g_deg[i] = 1;            // self-loop contributes 1
}

__global__ void k_hist(const void* ei, int E) {
    int i = blockIdx.x * blockDim.x + threadIdx.x;
    if (i >= E) return;
    int d = edge_val(ei, i, E, 1);
    atomicAdd(&g_deg[d], 1);
}

// 3-phase parallel exclusive scan of g_deg[0..n) -> g_off, g_cur, g_off[n]=total
__global__ void k_scan1(int n) {
    __shared__ int sh[1024];
    int tid = threadIdx.x;
    int i = blockIdx.x * 1024 + tid;
    int v = (i < n) ? g_deg[i] : 0;
    sh[tid] = v;
    __syncthreads();
    #pragma unroll
    for (int off = 1; off < 1024; off <<= 1) {
        int t = (tid >= off) ? sh[tid - off] : 0;
        __syncthreads();
        sh[tid] += t;
        __syncthreads();
    }
    if (i < n) g_incl[i] = sh[tid];
    if (tid == 1023) g_part[blockIdx.x] = sh[1023];
}

__global__ void k_scan2(int nb, int n) {
    __shared__ int sh[128];
    int tid = threadIdx.x;
    int v = (tid < nb) ? g_part[tid] : 0;
    sh[tid] = v;
    __syncthreads();
    #pragma unroll
    for (int off = 1; off < 128; off <<= 1) {
        int t = (tid >= off) ? sh[tid - off] : 0;
        __syncthreads();
        sh[tid] += t;
        __syncthreads();
    }
    if (tid < nb) g_partx[tid] = sh[tid] - v;
    if (tid == 127) g_off[n] = sh[127];
}

__global__ void k_scan3(int n) {
    int i = blockIdx.x * blockDim.x + threadIdx.x;
    if (i >= n) return;
    int ex = g_partx[i >> 10] + g_incl[i] - g_deg[i];
    g_off[i] = ex;
    g_cur[i] = ex;
}

__global__ void k_scatter(const void* ei, int E, int n) {
    int i = blockIdx.x * blockDim.x + threadIdx.x;
    if (i >= E + n) return;
    int s, d;
    if (i < E) { s = edge_val(ei, i, E, 0); d = edge_val(ei, i, E, 1); }
    else       { s = d = i - E; }       // self-loop
    int slot = atomicAdd(&g_cur[d], 1);
    g_csr[slot] = s;
}

// ---------------------------------------------------------------- SGEMM
// C[M,Ncol](fp16) = A[M,K](fp32) @ B[K,Ncol](fp32), row-major. BM=128, BN=64,
// BK=16, 256 threads, 8x4/thread, float4, register-staged double buffer.
__global__ __launch_bounds__(256) void k_sgemm(
    const float* __restrict__ A, const float* __restrict__ B,
    __half* __restrict__ C, int M, int K, int Ncol)
{
    __shared__ float As[16][132];
    __shared__ float Bs[16][64];
    int row0 = blockIdx.y * 128;
    int col0 = blockIdx.x * 64;
    int tid  = threadIdx.x;
    int tx   = tid & 15;            // column group (4 cols)
    int ty   = tid >> 4;            // row group (8 rows)
    float acc[8][4] = {};

    int am[2], akq[2];
    #pragma unroll
    for (int r = 0; r < 2; r++) {
        int id = tid + r * 256;
        am[r]  = id >> 2;
        akq[r] = id & 3;
    }
    int brow = tid >> 4;
    int bcq  = tid & 15;
    int bgc  = col0 + bcq * 4;

    #pragma unroll
    for (int r = 0; r < 2; r++) {
        int gr = row0 + am[r];
        float4 av = make_float4(0.f, 0.f, 0.f, 0.f);
        if (gr < M) av = *(const float4*)(A + (size_t)gr * K + akq[r] * 4);
        As[akq[r] * 4 + 0][am[r]] = av.x;
        As[akq[r] * 4 + 1][am[r]] = av.y;
        As[akq[r] * 4 + 2][am[r]] = av.z;
        As[akq[r] * 4 + 3][am[r]] = av.w;
    }
    {
        float4 bv = make_float4(0.f, 0.f, 0.f, 0.f);
        if (bgc < Ncol) bv = *(const float4*)(B + (size_t)brow * Ncol + bgc);
        *(float4*)&Bs[brow][bcq * 4] = bv;
    }
    __syncthreads();

    for (int k0 = 0; k0 < K; k0 += 16) {
        bool hasNext = (k0 + 16) < K;
        float4 an[2], bn;
        if (hasNext) {
            #pragma unroll
            for (int r = 0; r < 2; r++) {
                int gr = row0 + am[r];
                an[r] = make_float4(0.f, 0.f, 0.f, 0.f);
                if (gr < M) an[r] = *(const float4*)(A + (size_t)gr * K + k0 + 16 + akq[r] * 4);
            }
            bn = make_float4(0.f, 0.f, 0.f, 0.f);
            if (bgc < Ncol) bn = *(const float4*)(B + (size_t)(k0 + 16 + brow) * Ncol + bgc);
        }
        #pragma unroll
        for (int kk = 0; kk < 16; kk++) {
            float4 a0 = *(const float4*)&As[kk][ty * 8];
            float4 a1 = *(const float4*)&As[kk][ty * 8 + 4];
            float4 bv = *(const float4*)&Bs[kk][tx * 4];
            float a[8] = {a0.x, a0.y, a0.z, a0.w, a1.x, a1.y, a1.z, a1.w};
            float b[4] = {bv.x, bv.y, bv.z, bv.w};
            #pragma unroll
            for (int i = 0; i < 8; i++)
                #pragma unroll
                for (int j = 0; j < 4; j++)
                    acc[i][j] += a[i] * b[j];
        }
        if (hasNext) {
            __syncthreads();
            #pragma unroll
            for (int r = 0; r < 2; r++) {
                As[akq[r] * 4 + 0][am[r]] = an[r].x;
                As[akq[r] * 4 + 1][am[r]] = an[r].y;
                As[akq[r] * 4 + 2][am[r]] = an[r].z;
                As[akq[r] * 4 + 3][am[r]] = an[r].w;
            }
            *(float4*)&Bs[brow][bcq * 4] = bn;
            __syncthreads();
        }
    }
    #pragma unroll
    for (int i = 0; i < 8; i++) {
        int gr = row0 + ty * 8 + i;
        if (gr >= M) continue;
        int gc = col0 + tx * 4;
        if (gc < Ncol) {
            __half2 p0 = __floats2half2_rn(acc[i][0], acc[i][1]);
            __half2 p1 = __floats2half2_rn(acc[i][2], acc[i][3]);
            __half2* cp = (__half2*)(C + (size_t)gr * Ncol + gc);
            cp[0] = p0;
            cp[1] = p1;
        }
    }
}

// ---------------------------------------------------------------- attn logits
template <int H, int C>
__global__ void k_logits(const __half* __restrict__ feat,
                         const float* __restrict__ a_src,
                         const float* __restrict__ a_dst,
                         float* __restrict__ als, float* __restrict__ ald,
                         int n)
{
    int t = blockIdx.x * blockDim.x + threadIdx.x;
    if (t >= n * H) return;
    int nd = t / H, h = t % H;
    const __half2* row = (const __half2*)(feat + (size_t)nd * (H * C) + h * C);
    const float2* as2  = (const float2*)(a_src + h * C);
    const float2* ad2  = (const float2*)(a_dst + h * C);
    float ss = 0.f, sd = 0.f;
    #pragma unroll
    for (int c = 0; c < C / 2; c++) {
        float2 v = __half22float2(row[c]);
        float2 a = as2[c], d = ad2[c];
        ss += v.x * a.x + v.y * a.y;
        sd += v.x * d.x + v.y * d.y;
    }
    als[t] = ss;
    ald[t] = sd;
}

// ---------------------------------------------------------------- aggregate
// warp per node. feat fp16: lane l owns channels [8l, 8l+8) (one uint4 load
// per edge). C % 8 == 0 so each chunk lies in exactly one head. Softmax
// without max-shift (logits O(1); clamp@80 is a no-op safety). One MUFU
// warp-instr per edge. fp32 accumulate. Depth-2 src/payload pipeline.
template <int H, int C, bool RELU>
__global__ __launch_bounds__(256) void k_aggr(
    const __half* __restrict__ feat, const float* __restrict__ als,
    const float* __restrict__ aldv, const float* __restrict__ bias,
    float* __restrict__ out, int n)
{
    constexpr int HC  = H * C;
    constexpr int NCH = HC / 8;            // active lanes (28 / 24 / 30)
    const unsigned FULL = 0xffffffffu;
    int gw   = (blockIdx.x * blockDim.x + threadIdx.x) >> 5;
    int lane = threadIdx.x & 31;
    if (gw >= n) return;
    int beg = g_off[gw], end = g_off[gw + 1];

    bool act = lane < NCH;
    int  hA  = act ? (lane * 8) / C : 0;

    float aldL = (lane < H) ? aldv[gw * H + lane] : 0.f;
    float s = 0.f;
    float acc[8];
    #pragma unroll
    for (int j = 0; j < 8; j++) acc[j] = 0.f;

    union U4 { uint4 u; __half2 h[4]; };

    // pipeline prologue
    int src  = g_csr[beg];
    int srcA = (beg + 1 < end) ? g_csr[beg + 1] : src;
    float alsC = (lane < H) ? __ldg(als + (size_t)src * H + lane) : 0.f;
    U4 v; v.u = make_uint4(0, 0, 0, 0);
    if (act) v.u = __ldg((const uint4*)(feat + (size_t)src * HC) + lane);

    for (int i = beg; i < end; i++) {
        bool more = (i + 1 < end);
        int srcB = (i + 2 < end) ? g_csr[i + 2] : srcA;
        float alsN = 0.f;
        U4 vn; vn.u = make_uint4(0, 0, 0, 0);
        if (more) {
            alsN = (lane < H) ? __ldg(als + (size_t)srcA * H + lane) : 0.f;
            if (act) vn.u = __ldg((const uint4*)(feat + (size_t)srcA * HC) + lane);
        }
        // ---- process current edge
        float e = alsC + aldL;
        e = (e > 0.f) ? e : 0.2f * e;
        e = fminf(e, 80.f);
        float w = (lane < H) ? __expf(e) : 0.f;
        s += w;
        float wA = __shfl_sync(FULL, w, hA);
        #pragma unroll
        for (int j = 0; j < 4; j++) {
            float2 f = __half22float2(v.h[j]);
            acc[2 * j]     += wA * f.x;
            acc[2 * j + 1] += wA * f.y;
        }
        // ---- rotate
        alsC = alsN; v.u = vn.u; srcA = srcB;
    }

    float inv  = (lane < H) ? 1.f / s : 0.f;
    float invA = __shfl_sync(FULL, inv, hA);
    if (act) {
        const float4* b4 = (const float4*)(bias + lane * 8);
        float4 b0 = b4[0], b1 = b4[1];
        float4 o0, o1;
        o0.x = acc[0] * invA + b0.x; o0.y = acc[1] * invA + b0.y;
        o0.z = acc[2] * invA + b0.z; o0.w = acc[3] * invA + b0.w;
        o1.x = acc[4] * invA + b1.x; o1.y = acc[5] * invA + b1.y;
        o1.z = acc[6] * invA + b1.z; o1.w = acc[7] * invA + b1.w;
        if (RELU) {
            o0.x = fmaxf(o0.x, 0.f); o0.y = fmaxf(o0.y, 0.f);
            o0.z = fmaxf(o0.z, 0.f); o0.w = fmaxf(o0.w, 0.f);
            o1.x = fmaxf(o1.x, 0.f); o1.y = fmaxf(o1.y, 0.f);
            o1.z = fmaxf(o1.z, 0.f); o1.w = fmaxf(o1.w, 0.f);
        }
        float4* op = (float4*)(out + (size_t)gw * HC + lane * 8);
        op[0] = o0;
        op[1] = o1;
    }
}

// ---------------------------------------------------------------- launch
extern "C" void kernel_launch(void* const* d_in, const int* in_sizes, int n_in,
                              void* d_out, int out_size)
{
    const float* x   = (const float*)d_in[0];
    const void*  ei  = d_in[1];
    const float* W1  = (const float*)d_in[2];
    const float* a1s = (const float*)d_in[3];
    const float* a1d = (const float*)d_in[4];
    const float* b1  = (const float*)d_in[5];
    const float* W2  = (const float*)d_in[6];
    const float* a2s = (const float*)d_in[7];
    const float* a2d = (const float*)d_in[8];
    const float* b2  = (const float*)d_in[9];
    const float* W3  = (const float*)d_in[10];
    const float* a3s = (const float*)d_in[11];
    const float* a3d = (const float*)d_in[12];
    const float* b3  = (const float*)d_in[13];
    float* out = (float*)d_out;

    int E = in_sizes[1] / 2;
    int n = in_sizes[0] / 128;
    if (n > NMAX) n = NMAX;
    if (E + n > EMAX) E = EMAX - n;

    void *pf, *pb, *ps, *pd;
    cudaGetSymbolAddress(&pf, g_feat);
    cudaGetSymbolAddress(&pb, g_buf);
    cudaGetSymbolAddress(&ps, g_als);
    cudaGetSymbolAddress(&pd, g_ald);
    __half* feat = (__half*)pf;
    float*  buf  = (float*)pb;
    float*  als  = (float*)ps;
    float*  ald  = (float*)pd;

    // CSR build
    k_detect<<<1, 32>>>((const unsigned long long*)ei, E);
    k_init_deg<<<(n + 255) / 256, 256>>>(n);
    k_hist<<<(E + 255) / 256, 256>>>(ei, E);
    int nb = (n + 1023) / 1024;
    k_scan1<<<nb, 1024>>>(n);
    k_scan2<<<1, 128>>>(nb, n);
    k_scan3<<<(n + 255) / 256, 256>>>(n);
    k_scatter<<<(E + n + 255) / 256, 256>>>(ei, E, n);

    int wgrid = (n + 7) / 8;   // warp-per-node kernels, 8 warps/block

    // Layer 1: F=128 -> H=7,C=32
    {
        dim3 grid((224 + 63) / 64, (n + 127) / 128);
        k_sgemm<<<grid, 256>>>(x, W1, feat, n, 128, 224);
        int nh = n * 7;
        k_logits<7, 32><<<(nh + 255) / 256, 256>>>(feat, a1s, a1d, als, ald, n);
        k_aggr<7, 32, true><<<wgrid, 256>>>(feat, als, ald, b1, buf, n);
    }
    // Layer 2: F=224 -> H=6,C=32
    {
        dim3 grid((192 + 63) / 64, (n + 127) / 128);
        k_sgemm<<<grid, 256>>>(buf, W2, feat, n, 224, 192);
        int nh = n * 6;
        k_logits<6, 32><<<(nh + 255) / 256, 256>>>(feat, a2s, a2d, als, ald, n);
        k_aggr<6, 32, true><<<wgrid, 256>>>(feat, als, ald, b2, buf, n);
    }
    // Layer 3: F=192 -> H=6,C=40 -> d_out
    {
        dim3 grid((240 + 63) / 64, (n + 127) / 128);
        k_sgemm<<<grid, 256>>>(buf, W3, feat, n, 192, 240);
        int nh = n * 6;
        k_logits<6, 40><<<(nh + 255) / 256, 256>>>(feat, a3s, a3d, als, ald, n);
        k_aggr<6, 40, false><<<wgrid, 256>>>(feat, als, ald, b3, out, n);
    }
}

// round 7
// speedup vs baseline: 3.6372x; 1.5384x over previous
#include <cuda_runtime.h>
#include <cuda_fp16.h>
#include <cstdint>

// ---------------------------------------------------------------------------
// GAT_33938831573041: 3-layer GAT (PyG GATConv, concat=True, self-loops)
//   L1: F=128 -> H=7,C=32 (out 224) + relu
//   L2: F=224 -> H=6,C=32 (out 192) + relu
//   L3: F=192 -> H=6,C=40 (out 240)  -> d_out
// R7: GEMMs on tensor cores (mma.sync m16n8k16, fp16 in / fp32 acc),
//     fp16 activations end-to-end between layers, aggregation as R6.
// ---------------------------------------------------------------------------

#define NMAX 50000
#define EMAX 1200000

__device__ __align__(16) unsigned short g_feat[NMAX * 240];  // x@W (fp16)
__device__ __align__(16) unsigned short g_bufh[NMAX * 224];  // layer out (fp16)
__device__ __align__(16) unsigned short g_xh  [NMAX * 128];  // x as fp16
__device__ __align__(16) unsigned short g_w1h [128 * 224];
__device__ __align__(16) unsigned short g_w2h [224 * 192];
__device__ __align__(16) unsigned short g_w3h [192 * 240];
__device__ float g_als [NMAX * 7];
__device__ float g_ald [NMAX * 7];
__device__ int   g_deg [NMAX + 1];
__device__ int   g_off [NMAX + 1];
__device__ int   g_cur [NMAX];
__device__ int   g_incl[NMAX];
__device__ int   g_part[128];
__device__ int   g_partx[128];
__device__ int   g_csr [EMAX];
__device__ int   g_e64;

__device__ __forceinline__ uint32_t smem_u32(const void* p) {
    return (uint32_t)__cvta_generic_to_shared(p);
}

// ---------------------------------------------------------------- fp32->fp16
__global__ void k_cvt(const float* __restrict__ in, __half* __restrict__ out,
                      int cnt) {
    int i = (blockIdx.x * blockDim.x + threadIdx.x) * 2;
    if (i + 1 < cnt) {
        float2 v = *(const float2*)(in + i);
        *(__half2*)(out + i) = __floats2half2_rn(v.x, v.y);
    } else if (i < cnt) {
        out[i] = __float2half_rn(in[i]);
    }
}

// ---------------------------------------------------------------- dtype sniff
__global__ void k_detect(const unsigned long long* ei, int nwords) {
    int lane = threadIdx.x;
    int bad = 0;
    for (int i = lane; i < 64 && i < nwords; i += 32)
        if (ei[i] >= (1ull << 31)) bad = 1;
    unsigned m = __ballot_sync(0xffffffffu, bad);
    if (lane == 0) g_e64 = (m == 0);   // 1 => genuine int64 indices
}

__device__ __forceinline__ int edge_val(const void* ei, int idx, int E, int which) {
    if (g_e64) return (int)((const long long*)ei)[(size_t)which * E + idx];
    return ((const int*)ei)[(size_t)which * E + idx];
}

// ---------------------------------------------------------------- CSR build
__global__ void k_init_deg(int n) {
    int i = blockIdx.x * blockDim.x + threadIdx.x;
    if (i < n) g_deg[i] = 1;            // self-loop contributes 1
}

__global__ void k_hist(const void* ei, int E) {
    int i = blockIdx.x * blockDim.x + threadIdx.x;
    if (i >= E) return;
    int d = edge_val(ei, i, E, 1);
    atomicAdd(&g_deg[d], 1);
}

__global__ void k_scan1(int n) {
    __shared__ int sh[1024];
    int tid = threadIdx.x;
    int i = blockIdx.x * 1024 + tid;
    int v = (i < n) ? g_deg[i] : 0;
    sh[tid] = v;
    __syncthreads();
    #pragma unroll
    for (int off = 1; off < 1024; off <<= 1) {
        int t = (tid >= off) ? sh[tid - off] : 0;
        __syncthreads();
        sh[tid] += t;
        __syncthreads();
    }
    if (i < n) g_incl[i] = sh[tid];
    if (tid == 1023) g_part[blockIdx.x] = sh[1023];
}

__global__ void k_scan2(int nb, int n) {
    __shared__ int sh[128];
    int tid = threadIdx.x;
    int v = (tid < nb) ? g_part[tid] : 0;
    sh[tid] = v;
    __syncthreads();
    #pragma unroll
    for (int off = 1; off < 128; off <<= 1) {
        int t = (tid >= off) ? sh[tid - off] : 0;
        __syncthreads();
        sh[tid] += t;
        __syncthreads();
    }
    if (tid < nb) g_partx[tid] = sh[tid] - v;
    if (tid == 127) g_off[n] = sh[127];
}

__global__ void k_scan3(int n) {
    int i = blockIdx.x * blockDim.x + threadIdx.x;
    if (i >= n) return;
    int ex = g_partx[i >> 10] + g_incl[i] - g_deg[i];
    g_off[i] = ex;
    g_cur[i] = ex;
}

__global__ void k_scatter(const void* ei, int E, int n) {
    int i = blockIdx.x * blockDim.x + threadIdx.x;
    if (i >= E + n) return;
    int s, d;
    if (i < E) { s = edge_val(ei, i, E, 0); d = edge_val(ei, i, E, 1); }
    else       { s = d = i - E; }       // self-loop
    int slot = atomicAdd(&g_cur[d], 1);
    g_csr[slot] = s;
}

// ---------------------------------------------------------------- HGEMM (TC)
// C[M,N](fp16) = A[M,K](fp16) @ B[K,N](fp16), fp32 accumulate.
// BM=128, BN=64, BK=32; 8 warps, each 32x32 via 2x4 mma.m16n8k16 frags.
// A smem row stride 40 halves (80B), B stride 72 halves (144B): both make
// ldmatrix 8-row phases hit distinct 16B bank groups (conflict-free).
__global__ __launch_bounds__(256) void k_hgemm(
    const __half* __restrict__ A, const __half* __restrict__ B,
    __half* __restrict__ C, int M, int K, int Ncol)
{
    __shared__ __align__(16) __half As[128 * 40];
    __shared__ __align__(16) __half Bs[32 * 72];
    const int tid  = threadIdx.x;
    const int lane = tid & 31;
    const int wid  = tid >> 5;
    const int wm   = (wid & 3) * 32;
    const int wn   = (wid >> 2) * 32;
    const int row0 = blockIdx.y * 128;
    const int col0 = blockIdx.x * 64;

    float acc[2][4][4];
    #pragma unroll
    for (int a = 0; a < 2; a++)
        #pragma unroll
        for (int b = 0; b < 4; b++)
            #pragma unroll
            for (int c = 0; c < 4; c++) acc[a][b][c] = 0.f;

    int ar[2], ac[2];
    #pragma unroll
    for (int r = 0; r < 2; r++) {
        int id = tid + r * 256;
        ar[r] = id >> 2;
        ac[r] = (id & 3) * 8;
    }
    const int br = tid >> 3;
    const int bc = (tid & 7) * 8;

    // prologue: tile 0 gmem -> smem
    #pragma unroll
    for (int r = 0; r < 2; r++) {
        int gr = row0 + ar[r];
        uint4 u = make_uint4(0, 0, 0, 0);
        if (gr < M) u = *(const uint4*)(A + (size_t)gr * K + ac[r]);
        *(uint4*)&As[ar[r] * 40 + ac[r]] = u;
    }
    {
        int gc = col0 + bc;
        uint4 u = make_uint4(0, 0, 0, 0);
        if (gc < Ncol) u = *(const uint4*)(B + (size_t)br * Ncol + gc);
        *(uint4*)&Bs[br * 72 + bc] = u;
    }
    __syncthreads();

    for (int k0 = 0; k0 < K; k0 += 32) {
        bool hasNext = (k0 + 32) < K;
        uint4 an[2], bn;
        if (hasNext) {
            #pragma unroll
            for (int r = 0; r < 2; r++) {
                int gr = row0 + ar[r];
                an[r] = make_uint4(0, 0, 0, 0);
                if (gr < M) an[r] = *(const uint4*)(A + (size_t)gr * K + k0 + 32 + ac[r]);
            }
            int gc = col0 + bc;
            bn = make_uint4(0, 0, 0, 0);
            if (gc < Ncol) bn = *(const uint4*)(B + (size_t)(k0 + 32 + br) * Ncol + gc);
        }
        #pragma unroll
        for (int ks = 0; ks < 32; ks += 16) {
            uint32_t af[2][4], bf[2][4];
            #pragma unroll
            for (int fm = 0; fm < 2; fm++) {
                uint32_t addr = smem_u32(
                    &As[(wm + fm * 16 + (lane & 15)) * 40 + ks + (lane >> 4) * 8]);
                asm volatile(
                    "ldmatrix.sync.aligned.m8n8.x4.shared.b16 {%0,%1,%2,%3}, [%4];"
                    : "=r"(af[fm][0]), "=r"(af[fm][1]),
                      "=r"(af[fm][2]), "=r"(af[fm][3]) : "r"(addr));
            }
            #pragma unroll
            for (int bb = 0; bb < 2; bb++) {
                uint32_t addr = smem_u32(
                    &Bs[(ks + (lane & 15)) * 72 + wn + bb * 16 + (lane >> 4) * 8]);
                asm volatile(
                    "ldmatrix.sync.aligned.m8n8.x4.trans.shared.b16 {%0,%1,%2,%3}, [%4];"
                    : "=r"(bf[bb][0]), "=r"(bf[bb][1]),
                      "=r"(bf[bb][2]), "=r"(bf[bb][3]) : "r"(addr));
            }
            #pragma unroll
            for (int fm = 0; fm < 2; fm++)
                #pragma unroll
                for (int fn = 0; fn < 4; fn++) {
                    uint32_t b0 = bf[fn >> 1][(fn & 1) * 2];
                    uint32_t b1 = bf[fn >> 1][(fn & 1) * 2 + 1];
                    asm volatile(
                        "mma.sync.aligned.m16n8k16.row.col.f32.f16.f16.f32 "
                        "{%0,%1,%2,%3}, {%4,%5,%6,%7}, {%8,%9}, {%0,%1,%2,%3};"
                        : "+f"(acc[fm][fn][0]), "+f"(acc[fm][fn][1]),
                          "+f"(acc[fm][fn][2]), "+f"(acc[fm][fn][3])
                        : "r"(af[fm][0]), "r"(af[fm][1]),
                          "r"(af[fm][2]), "r"(af[fm][3]),
                          "r"(b0), "r"(b1));
                }
        }
        if (hasNext) {
            __syncthreads();
            #pragma unroll
            for (int r = 0; r < 2; r++)
                *(uint4*)&As[ar[r] * 40 + ac[r]] = an[r];
            *(uint4*)&Bs[br * 72 + bc] = bn;
            __syncthreads();
        }
    }

    // epilogue: c0,c1 -> (r, c..c+1); c2,c3 -> (r+8, c..c+1)
    int rr = lane >> 2, cc = (lane & 3) * 2;
    #pragma unroll
    for (int fm = 0; fm < 2; fm++)
        #pragma unroll
        for (int fn = 0; fn < 4; fn++) {
            int gr0 = row0 + wm + fm * 16 + rr;
            int gc  = col0 + wn + fn * 8 + cc;
            if (gc < Ncol) {
                if (gr0 < M)
                    *(__half2*)(C + (size_t)gr0 * Ncol + gc) =
                        __floats2half2_rn(acc[fm][fn][0], acc[fm][fn][1]);
                if (gr0 + 8 < M)
                    *(__half2*)(C + (size_t)(gr0 + 8) * Ncol + gc) =
                        __floats2half2_rn(acc[fm][fn][2], acc[fm][fn][3]);
            }
        }
}

// ---------------------------------------------------------------- attn logits
template <int H, int C>
__global__ void k_logits(const __half* __restrict__ feat,
                         const float* __restrict__ a_src,
                         const float* __restrict__ a_dst,
                         float* __restrict__ als, float* __restrict__ ald,
                         int n)
{
    int t = blockIdx.x * blockDim.x + threadIdx.x;
    if (t >= n * H) return;
    int nd = t / H, h = t % H;
    const __half2* row = (const __half2*)(feat + (size_t)nd * (H * C) + h * C);
    const float2* as2  = (const float2*)(a_src + h * C);
    const float2* ad2  = (const float2*)(a_dst + h * C);
    float ss = 0.f, sd = 0.f;
    #pragma unroll
    for (int c = 0; c < C / 2; c++) {
        float2 v = __half22float2(row[c]);
        float2 a = as2[c], d = ad2[c];
        ss += v.x * a.x + v.y * a.y;
        sd += v.x * d.x + v.y * d.y;
    }
    als[t] = ss;
    ald[t] = sd;
}

// ---------------------------------------------------------------- aggregate
// warp per node. feat fp16: lane l owns channels [8l, 8l+8) (one uint4 load
// per edge). C % 8 == 0 so each chunk lies in exactly one head. Softmax
// without max-shift (logits O(1); clamp@80 safety). One MUFU warp-instr per
// edge. fp32 accumulate. OUTHALF: store fp16 (next layer input) vs fp32.
template <int H, int C, bool RELU, bool OUTHALF>
__global__ __launch_bounds__(256) void k_aggr(
    const __half* __restrict__ feat, const float* __restrict__ als,
    const float* __restrict__ aldv, const float* __restrict__ bias,
    void* __restrict__ outv, int n)
{
    constexpr int HC  = H * C;
    constexpr int NCH = HC / 8;            // active lanes (28 / 24 / 30)
    const unsigned FULL = 0xffffffffu;
    int gw   = (blockIdx.x * blockDim.x + threadIdx.x) >> 5;
    int lane = threadIdx.x & 31;
    if (gw >= n) return;
    int beg = g_off[gw], end = g_off[gw + 1];

    bool act = lane < NCH;
    int  hA  = act ? (lane * 8) / C : 0;

    float aldL = (lane < H) ? aldv[gw * H + lane] : 0.f;
    float s = 0.f;
    float acc[8];
    #pragma unroll
    for (int j = 0; j < 8; j++) acc[j] = 0.f;

    union U4 { uint4 u; __half2 h[4]; };

    int src  = g_csr[beg];
    int srcA = (beg + 1 < end) ? g_csr[beg + 1] : src;
    float alsC = (lane < H) ? __ldg(als + (size_t)src * H + lane) : 0.f;
    U4 v; v.u = make_uint4(0, 0, 0, 0);
    if (act) v.u = __ldg((const uint4*)(feat + (size_t)src * HC) + lane);

    for (int i = beg; i < end; i++) {
        bool more = (i + 1 < end);
        int srcB = (i + 2 < end) ? g_csr[i + 2] : srcA;
        float alsN = 0.f;
        U4 vn; vn.u = make_uint4(0, 0, 0, 0);
        if (more) {
            alsN = (lane < H) ? __ldg(als + (size_t)srcA * H + lane) : 0.f;
            if (act) vn.u = __ldg((const uint4*)(feat + (size_t)srcA * HC) + lane);
        }
        float e = alsC + aldL;
        e = (e > 0.f) ? e : 0.2f * e;
        e = fminf(e, 80.f);
        float w = (lane < H) ? __expf(e) : 0.f;
        s += w;
        float wA = __shfl_sync(FULL, w, hA);
        #pragma unroll
        for (int j = 0; j < 4; j++) {
            float2 f = __half22float2(v.h[j]);
            acc[2 * j]     += wA * f.x;
            acc[2 * j + 1] += wA * f.y;
        }
        alsC = alsN; v.u = vn.u; srcA = srcB;
    }

    float inv  = (lane < H) ? 1.f / s : 0.f;
    float invA = __shfl_sync(FULL, inv, hA);
    if (act) {
        const float4* b4 = (const float4*)(bias + lane * 8);
        float4 b0 = b4[0], b1 = b4[1];
        float o[8];
        o[0] = acc[0] * invA + b0.x; o[1] = acc[1] * invA + b0.y;
        o[2] = acc[2] * invA + b0.z; o[3] = acc[3] * invA + b0.w;
        o[4] = acc[4] * invA + b1.x; o[5] = acc[5] * invA + b1.y;
        o[6] = acc[6] * invA + b1.z; o[7] = acc[7] * invA + b1.w;
        if (RELU) {
            #pragma unroll
            for (int j = 0; j < 8; j++) o[j] = fmaxf(o[j], 0.f);
        }
        if (OUTHALF) {
            __half2 hs[4];
            #pragma unroll
            for (int j = 0; j < 4; j++)
                hs[j] = __floats2half2_rn(o[2 * j], o[2 * j + 1]);
            *(uint4*)((__half*)outv + (size_t)gw * HC + lane * 8) = *(uint4*)hs;
        } else {
            float4* op = (float4*)((float*)outv + (size_t)gw * HC + lane * 8);
            op[0] = make_float4(o[0], o[1], o[2], o[3]);
            op[1] = make_float4(o[4], o[5], o[6], o[7]);
        }
    }
}

// ---------------------------------------------------------------- launch
extern "C" void kernel_launch(void* const* d_in, const int* in_sizes, int n_in,
                              void* d_out, int out_size)
{
    const float* x   = (const float*)d_in[0];
    const void*  ei  = d_in[1];
    const float* W1  = (const float*)d_in[2];
    const float* a1s = (const float*)d_in[3];
    const float* a1d = (const float*)d_in[4];
    const float* b1  = (const float*)d_in[5];
    const float* W2  = (const float*)d_in[6];
    const float* a2s = (const float*)d_in[7];
    const float* a2d = (const float*)d_in[8];
    const float* b2  = (const float*)d_in[9];
    const float* W3  = (const float*)d_in[10];
    const float* a3s = (const float*)d_in[11];
    const float* a3d = (const float*)d_in[12];
    const float* b3  = (const float*)d_in[13];
    float* out = (float*)d_out;

    int E = in_sizes[1] / 2;
    int n = in_sizes[0] / 128;
    if (n > NMAX) n = NMAX;
    if (E + n > EMAX) E = EMAX - n;

    void *pf, *pb, *ps, *pd, *px, *pw1, *pw2, *pw3;
    cudaGetSymbolAddress(&pf, g_feat);
    cudaGetSymbolAddress(&pb, g_bufh);
    cudaGetSymbolAddress(&ps, g_als);
    cudaGetSymbolAddress(&pd, g_ald);
    cudaGetSymbolAddress(&px, g_xh);
    cudaGetSymbolAddress(&pw1, g_w1h);
    cudaGetSymbolAddress(&pw2, g_w2h);
    cudaGetSymbolAddress(&pw3, g_w3h);
    __half* feat = (__half*)pf;
    __half* bufh = (__half*)pb;
    __half* xh   = (__half*)px;
    __half* w1h  = (__half*)pw1;
    __half* w2h  = (__half*)pw2;
    __half* w3h  = (__half*)pw3;
    float*  als  = (float*)ps;
    float*  ald  = (float*)pd;

    // fp16 conversions
    {
        int c0 = n * 128;
        k_cvt<<<(c0 / 2 + 255) / 256, 256>>>(x, xh, c0);
        k_cvt<<<(128 * 224 / 2 + 255) / 256, 256>>>(W1, w1h, 128 * 224);
        k_cvt<<<(224 * 192 / 2 + 255) / 256, 256>>>(W2, w2h, 224 * 192);
        k_cvt<<<(192 * 240 / 2 + 255) / 256, 256>>>(W3, w3h, 192 * 240);
    }

    // CSR build
    k_detect<<<1, 32>>>((const unsigned long long*)ei, E);
    k_init_deg<<<(n + 255) / 256, 256>>>(n);
    k_hist<<<(E + 255) / 256, 256>>>(ei, E);
    int nb = (n + 1023) / 1024;
    k_scan1<<<nb, 1024>>>(n);
    k_scan2<<<1, 128>>>(nb, n);
    k_scan3<<<(n + 255) / 256, 256>>>(n);
    k_scatter<<<(E + n + 255) / 256, 256>>>(ei, E, n);

    int wgrid = (n + 7) / 8;   // warp-per-node kernels, 8 warps/block

    // Layer 1: F=128 -> H=7,C=32
    {
        dim3 grid((224 + 63) / 64, (n + 127) / 128);
        k_hgemm<<<grid, 256>>>(xh, w1h, feat, n, 128, 224);
        int nh = n * 7;
        k_logits<7, 32><<<(nh + 255) / 256, 256>>>(feat, a1s, a1d, als, ald, n);
        k_aggr<7, 32, true, true><<<wgrid, 256>>>(feat, als, ald, b1, bufh, n);
    }
    // Layer 2: F=224 -> H=6,C=32
    {
        dim3 grid((192 + 63) / 64, (n + 127) / 128);
        k_hgemm<<<grid, 256>>>(bufh, w2h, feat, n, 224, 192);
        int nh = n * 6;
        k_logits<6, 32><<<(nh + 255) / 256, 256>>>(feat, a2s, a2d, als, ald, n);
        k_aggr<6, 32, true, true><<<wgrid, 256>>>(feat, als, ald, b2, bufh, n);
    }
    // Layer 3: F=192 -> H=6,C=40 -> d_out
    {
        dim3 grid((240 + 63) / 64, (n + 127) / 128);
        k_hgemm<<<grid, 256>>>(bufh, w3h, feat, n, 192, 240);
        int nh = n * 6;
        k_logits<6, 40><<<(nh + 255) / 256, 256>>>(feat, a3s, a3d, als, ald, n);
        k_aggr<6, 40, false, false><<<wgrid, 256>>>(feat, als, ald, b3, out, n);
    }
}